// round 5
// baseline (speedup 1.0000x reference)
#include <cuda_runtime.h>

// EPS_68771016344265: 2x2 tensor-network contraction, S=2, OUT=4
// out[b,h,w,o] = sum_{s0..s3} x_h[w][s0] x_h[w+1][s1] x_{h+1}[w][s2] x_{h+1}[w+1][s3]
//               * core[s0,s1,s2,s3,o]
// q(h) = x_h[w] (x) x_h[w+1];  d(h)_j = sum_i q(h)_i C[i][j][:];  out(h) = sum_j q(h+1)_j d(h)_j
//
// o-dim split across thread pairs: even lane -> o{0,1}, odd lane -> o{2,3}.
// Per-thread core = 16 f32x2 pairs = 32 regs -> genuinely register-resident (no spills).

#define NB 128
#define NH 128
#define NW 128
#define HN 127
#define WN 127
#define TH 16

typedef unsigned long long u64;

__device__ __forceinline__ u64 f2mul(u64 a, u64 b) {
    u64 r; asm("mul.rn.f32x2 %0,%1,%2;" : "=l"(r) : "l"(a), "l"(b)); return r;
}
__device__ __forceinline__ u64 f2fma(u64 a, u64 b, u64 c) {
    u64 r; asm("fma.rn.f32x2 %0,%1,%2,%3;" : "=l"(r) : "l"(a), "l"(b), "l"(c)); return r;
}
__device__ __forceinline__ u64 fdup(float x) {
    u64 r; asm("mov.b64 %0,{%1,%1};" : "=l"(r) : "f"(x)); return r;
}
__device__ __forceinline__ float2 f2unpack(u64 a) {
    float2 v; asm("mov.b64 {%0,%1},%2;" : "=f"(v.x), "=f"(v.y) : "l"(a)); return v;
}

__global__ __launch_bounds__(128, 7)
void eps_kernel(const float* __restrict__ in,
                const float* __restrict__ core,
                float2* __restrict__ out)
{
    const int lane = threadIdx.x;
    const int w    = blockIdx.y * 64 + (lane >> 1);   // 0..127
    const int op   = lane & 1;                        // which o-pair this thread owns
    const int b    = blockIdx.z;
    const int h0   = blockIdx.x * TH;
    const int h1   = min(h0 + TH, HN);                // pixel rows [h0, h1)

    // Per-thread half-core: c[k] = {core[k][2*op], core[k][2*op+1]}, k = s0*8+s1*4+s2*2+s3
    u64 c[16];
    {
        const u64* cp = reinterpret_cast<const u64*>(core);
        #pragma unroll
        for (int k = 0; k < 16; k++) c[k] = cp[2 * k + op];
    }

    const float2* ip = reinterpret_cast<const float2*>(in);
    const int wp1 = (w < NW - 1) ? (w + 1) : w;       // clamp; w=127 never stores
    int inoff  = (b * NH + h0) * NW;                  // float2 index of row start
    int outoff = ((b * HN + h0) * WN + w) * 2 + op;   // float2 index into out

    // ---- row h0: q and d ----
    float2 xa = ip[inoff + w];
    float2 xb = ip[inoff + wp1];
    u64 q0 = fdup(xa.x * xb.x);
    u64 q1 = fdup(xa.x * xb.y);
    u64 q2 = fdup(xa.y * xb.x);
    u64 q3 = fdup(xa.y * xb.y);

    u64 d[4];
    #pragma unroll
    for (int j = 0; j < 4; j++)
        d[j] = f2fma(q3, c[12+j], f2fma(q2, c[8+j], f2fma(q1, c[4+j], f2mul(q0, c[j]))));

    const bool st = (w < WN);

    #pragma unroll 4
    for (int r = h0 + 1; r <= h1; ++r) {
        inoff += NW;
        xa = ip[inoff + w];
        xb = ip[inoff + wp1];
        q0 = fdup(xa.x * xb.x);
        q1 = fdup(xa.x * xb.y);
        q2 = fdup(xa.y * xb.x);
        q3 = fdup(xa.y * xb.y);

        // pixel (r-1): this thread's o-pair = sum_j q(r)_j * d(r-1)_j
        u64 o2 = f2fma(q3, d[3], f2fma(q2, d[2], f2fma(q1, d[1], f2mul(q0, d[0]))));
        if (st) out[outoff] = f2unpack(o2);
        outoff += 2 * WN;

        // d(r) for the next pixel (unconditional; waste only on the final iteration)
        #pragma unroll
        for (int j = 0; j < 4; j++)
            d[j] = f2fma(q3, c[12+j], f2fma(q2, c[8+j], f2fma(q1, c[4+j], f2mul(q0, c[j]))));
    }
}

extern "C" void kernel_launch(void* const* d_in, const int* in_sizes, int n_in,
                              void* d_out, int out_size)
{
    const float* in   = (const float*)d_in[0];   // (1,128,128,128,2) f32
    const float* core = (const float*)d_in[1];   // (2,2,2,2,4) f32
    float2* out = (float2*)d_out;                // (128,127,127,4) f32 viewed as float2

    dim3 grid((HN + TH - 1) / TH, 2, NB);        // (8, 2, 128) = 2048 blocks
    eps_kernel<<<grid, 128>>>(in, core, out);
}

// round 10
// speedup vs baseline: 1.1400x; 1.1400x over previous
#include <cuda_runtime.h>

// EPS_68771016344265: 2x2 tensor-network contraction, S=2, OUT=4
// out[b,h,w,o] = sum_{s0..s3} x_h[w][s0] x_h[w+1][s1] x_{h+1}[w][s2] x_{h+1}[w+1][s3]
//               * core[s0,s1,s2,s3,o]
// q(h) = x_h[w] (x) x_h[w+1];  d(h)_j = sum_i q(h)_i C[i][j][:];  out(h) = sum_j q(h+1)_j d(h)_j
//
// o-dim split across thread pairs (even lane -> o{0,1}, odd -> o{2,3}) so the per-thread
// half-core is 16 f32x2 = 32 regs. Strip loop fully unrolled with COMPILE-TIME trip count
// (fast path: 16 rows; last strip: 15 rows) so all input loads become LDG [base + imm]
// and ptxas can front-batch them for high MLP (DRAM latency was the R5 limiter).

#define NB 128
#define NH 128
#define NW 128
#define HN 127
#define WN 127
#define TH 16

typedef unsigned long long u64;

__device__ __forceinline__ u64 f2mul(u64 a, u64 b) {
    u64 r; asm("mul.rn.f32x2 %0,%1,%2;" : "=l"(r) : "l"(a), "l"(b)); return r;
}
__device__ __forceinline__ u64 f2fma(u64 a, u64 b, u64 c) {
    u64 r; asm("fma.rn.f32x2 %0,%1,%2,%3;" : "=l"(r) : "l"(a), "l"(b), "l"(c)); return r;
}
__device__ __forceinline__ u64 fdup(float x) {
    u64 r; asm("mov.b64 %0,{%1,%1};" : "=l"(r) : "f"(x)); return r;
}
__device__ __forceinline__ float2 f2unpack(u64 a) {
    float2 v; asm("mov.b64 {%0,%1},%2;" : "=f"(v.x), "=f"(v.y) : "l"(a)); return v;
}

template <int NROWS>   // number of pixel rows in this strip (compile-time)
__device__ __forceinline__ void run_strip(const float2* __restrict__ ip,   // row h0, float2 units
                                          const u64* __restrict__ c,
                                          float2* __restrict__ outp,      // pixel (h0, w), o-pair slot
                                          int w, int wp1, bool st)
{
    // row h0
    float2 xa = ip[w];
    float2 xb = ip[wp1];
    u64 q0 = fdup(xa.x * xb.x);
    u64 q1 = fdup(xa.x * xb.y);
    u64 q2 = fdup(xa.y * xb.x);
    u64 q3 = fdup(xa.y * xb.y);

    u64 d[4];
    #pragma unroll
    for (int j = 0; j < 4; j++)
        d[j] = f2fma(q3, c[12+j], f2fma(q2, c[8+j], f2fma(q1, c[4+j], f2mul(q0, c[j]))));

    #pragma unroll
    for (int k = 1; k <= NROWS; ++k) {
        // loads have compile-time offsets -> LDG [base + imm], batchable
        float2 ya = ip[k * NW + w];
        float2 yb = ip[k * NW + wp1];
        u64 p0 = fdup(ya.x * yb.x);
        u64 p1 = fdup(ya.x * yb.y);
        u64 p2 = fdup(ya.y * yb.x);
        u64 p3 = fdup(ya.y * yb.y);

        // pixel row h0+k-1: this thread's o-pair = sum_j p_j * d_j
        u64 o2 = f2fma(p3, d[3], f2fma(p2, d[2], f2fma(p1, d[1], f2mul(p0, d[0]))));
        if (st) outp[(k - 1) * 2 * WN] = f2unpack(o2);

        if (k < NROWS) {   // d for next pixel; dead on the last row
            #pragma unroll
            for (int j = 0; j < 4; j++)
                d[j] = f2fma(p3, c[12+j], f2fma(p2, c[8+j], f2fma(p1, c[4+j], f2mul(p0, c[j]))));
        }
    }
}

__global__ __launch_bounds__(128, 6)
void eps_kernel(const float* __restrict__ in,
                const float* __restrict__ core,
                float2* __restrict__ out)
{
    const int lane = threadIdx.x;
    const int slot = lane >> 1;
    const int op   = lane & 1;                       // which o-pair this thread owns
    const int w    = blockIdx.y * 64 + slot;         // 0..127
    const int b    = blockIdx.z;
    const int h0   = blockIdx.x * TH;

    // Per-thread half-core: c[k] = {core[k][2*op], core[k][2*op+1]}
    u64 c[16];
    {
        const u64* cp = reinterpret_cast<const u64*>(core);
        #pragma unroll
        for (int k = 0; k < 16; k++) c[k] = cp[2 * k + op];
    }

    const float2* ip = reinterpret_cast<const float2*>(in) + (b * NH + h0) * NW;
    const int wp1 = (w < NW - 1) ? (w + 1) : w;      // clamp; w=127 never stores
    float2* outp = out + ((long)(b * HN + h0) * WN + w) * 2 + op;
    const bool st = (w < WN);

    if (h0 + TH < HN) {
        // strips 0..6: 16 pixel rows, 17 input rows (max input row 96+16=112 < 128)
        run_strip<TH>(ip, c, outp, w, wp1, st);
    } else {
        // strip 7 (h0=112): 15 pixel rows (112..126), input rows 112..127
        run_strip<HN - 7 * TH>(ip, c, outp, w, wp1, st);
    }
}

extern "C" void kernel_launch(void* const* d_in, const int* in_sizes, int n_in,
                              void* d_out, int out_size)
{
    const float* in   = (const float*)d_in[0];   // (1,128,128,128,2) f32
    const float* core = (const float*)d_in[1];   // (2,2,2,2,4) f32
    float2* out = (float2*)d_out;                // (128,127,127,4) f32 viewed as float2

    dim3 grid((HN + TH - 1) / TH, 2, NB);        // (8, 2, 128) = 2048 blocks
    eps_kernel<<<grid, 128>>>(in, core, out);
}